// round 14
// baseline (speedup 1.0000x reference)
#include <cuda_runtime.h>
#include <cuda_fp16.h>
#include <cstdint>

#define NSEQ 8192
#define DIM  1024

// ---------------- scratch (module statics; no runtime allocation) ----------
__device__ __half g_qk16[2][(size_t)NSEQ * DIM];       // q,k fp16 (adjacent)
__device__ __half g_v16[(size_t)NSEQ * DIM];
__device__ __half g_WT[3][(size_t)DIM * DIM];          // Wq^T, Wk^T, Wv^T fp16
__device__ __half g_QK[2][(size_t)NSEQ * DIM];         // Q,K projections (adjacent)
__device__ __half g_Vr[(size_t)NSEQ * DIM];
__device__ __half g_VT[(size_t)DIM * NSEQ];
__device__ float  g_S [(size_t)NSEQ * NSEQ];
__device__ __half g_P [(size_t)NSEQ * NSEQ];
#define NSEG 8
__device__ float  g_Opart[NSEG][(size_t)NSEQ * DIM];   // PV split-K partials

#define PSCALE     4096.0f
#define PSCALE_INV 2.44140625e-4f   // 1/4096, exact

// ---------------- helpers ---------------------------------------------------
__device__ __forceinline__ uint32_t smem_u32(const void* p) {
    uint32_t a;
    asm("{ .reg .u64 t; cvta.to.shared.u64 t, %1; cvt.u32.u64 %0, t; }"
        : "=r"(a) : "l"(p));
    return a;
}
#define SWZ128(off) ((off) ^ (((off) >> 3) & 0x70))

__device__ __forceinline__ void ldm_x4(uint32_t* r, uint32_t addr) {
    asm volatile("ldmatrix.sync.aligned.m8n8.x4.shared.b16 {%0,%1,%2,%3}, [%4];"
                 : "=r"(r[0]), "=r"(r[1]), "=r"(r[2]), "=r"(r[3]) : "r"(addr));
}
__device__ __forceinline__ void mma_f16(float* c, const uint32_t* a,
                                        const uint32_t* b) {
    asm volatile(
        "mma.sync.aligned.m16n8k16.row.col.f32.f16.f16.f32 "
        "{%0,%1,%2,%3}, {%4,%5,%6,%7}, {%8,%9}, {%0,%1,%2,%3};"
        : "+f"(c[0]), "+f"(c[1]), "+f"(c[2]), "+f"(c[3])
        : "r"(a[0]), "r"(a[1]), "r"(a[2]), "r"(a[3]), "r"(b[0]), "r"(b[1]));
}
__device__ __forceinline__ void cpa16(uint32_t dst, const void* src) {
    asm volatile("cp.async.cg.shared.global [%0], [%1], 16;"
                 :: "r"(dst), "l"(src));
}
#define CPA_COMMIT() asm volatile("cp.async.commit_group;" ::: "memory")
#define CPA_WAIT1()  asm volatile("cp.async.wait_group 1;" ::: "memory")

__device__ __forceinline__ uint16_t h16(__half h) {
    return *reinterpret_cast<uint16_t*>(&h);
}

// ---------------------------------------------------------------------------
// 1-term fp16 NT GEMM: C[M,N] = alpha * A[M,K] @ B[N,K]^T, K-major operands.
// CTA 256x128, warp 64x64 (8 warps), BK=64, 2-stage cp.async (96 KB smem).
// cmode: 0 plain; 1 causal tile skip; 3 causal split-K (seg z over kcount
//        chunks, k-limit 4*(by+1), C += z*zsC).
// omode: 0 -> C fp32; 2 -> Ch fp16.
// zsA/zsB/zsC: per-z pointer strides for batched launches (cmode 0).
// ---------------------------------------------------------------------------
#define BM 256
#define BN 128
#define BK 64
#define SLAB_A (BM * BK * 2)               // 32 KB
#define SLAB_B (BN * BK * 2)               // 16 KB
#define STAGEB (SLAB_A + SLAB_B)           // 48 KB
#define SMEM_GEMM_BYTES (2 * STAGEB)       // 96 KB

__device__ __forceinline__ void issue_chunk(
    uint32_t sstage,
    const __half* __restrict__ Ah, const __half* __restrict__ Bh,
    int lda, int ldb, int row0, int col0, int kt, int tid)
{
#pragma unroll
    for (int i = 0; i < 8; i++) {          // A: 2048 16B chunks
        const int idx = i * 256 + tid;
        const int row = idx >> 3, c = idx & 7;
        const uint32_t off = SWZ128((uint32_t)(row * 128 + c * 16));
        const size_t g = (size_t)(row0 + row) * lda + (size_t)kt * BK + c * 8;
        cpa16(sstage + off, Ah + g);
    }
#pragma unroll
    for (int i = 0; i < 4; i++) {          // B: 1024 16B chunks
        const int idx = i * 256 + tid;
        const int row = idx >> 3, c = idx & 7;
        const uint32_t off = SWZ128((uint32_t)(row * 128 + c * 16));
        const size_t g = (size_t)(col0 + row) * ldb + (size_t)kt * BK + c * 8;
        cpa16(sstage + SLAB_A + off, Bh + g);
    }
}

__global__ void __launch_bounds__(256)
gemm_nt(const __half* __restrict__ Ah, const __half* __restrict__ Bh,
        float* __restrict__ C, __half* __restrict__ Ch,
        int lda, int ldb, int ldc, float alpha, int kcount,
        int cmode, int omode, size_t zsA, size_t zsB, size_t zsC)
{
    extern __shared__ char smem[];
    const int tid  = threadIdx.x;
    const int wid  = tid >> 5;
    const int lane = tid & 31;
    const int row0 = blockIdx.y * BM;
    const int col0 = blockIdx.x * BN;
    const int z    = blockIdx.z;

    if (cmode == 1 && col0 >= row0 + BM) return;

    if (zsA) Ah += (size_t)z * zsA;
    if (zsB) Bh += (size_t)z * zsB;

    int kbeg = 0;
    int kend = kcount;
    if (cmode == 3) {
        kbeg = z * kcount;
        const int klim = 4 * (blockIdx.y + 1);
        kend = min(kbeg + kcount, klim);
        if (kbeg >= kend) return;
        C += (size_t)z * zsC;
    } else if (zsC && Ch) {
        Ch += (size_t)z * zsC;
    }
    const int nch = kend - kbeg;

    const int wm = (wid & 3) * 64;
    const int wn = (wid >> 2) * 64;

    float acc[4][8][4];
#pragma unroll
    for (int i = 0; i < 4; i++)
#pragma unroll
        for (int j = 0; j < 8; j++)
#pragma unroll
            for (int r = 0; r < 4; r++) acc[i][j][r] = 0.f;

    const uint32_t sb = smem_u32(smem);

    issue_chunk(sb, Ah, Bh, lda, ldb, row0, col0, kbeg, tid);
    CPA_COMMIT();
    if (nch > 1)
        issue_chunk(sb + STAGEB, Ah, Bh, lda, ldb, row0, col0, kbeg + 1, tid);
    CPA_COMMIT();

    for (int i = 0; i < nch; i++) {
        const int st = i & 1;
        CPA_WAIT1();
        __syncthreads();

        const uint32_t sAh = sb + st * STAGEB;
        const uint32_t sBh = sAh + SLAB_A;

#pragma unroll
        for (int ks = 0; ks < 4; ks++) {
            uint32_t bh[4][4];
#pragma unroll
            for (int np = 0; np < 4; np++) {
                const uint32_t roff = SWZ128((uint32_t)(
                    (wn + np * 16 + ((lane >> 4) << 3) + (lane & 7)) * 128 +
                    ks * 32 + ((lane >> 3) & 1) * 16));
                ldm_x4(bh[np], sBh + roff);
            }
#pragma unroll
            for (int mf = 0; mf < 4; mf++) {
                const uint32_t aoff = SWZ128((uint32_t)(
                    (wm + mf * 16 + (lane & 15)) * 128 +
                    ks * 32 + ((lane >> 4) & 1) * 16));
                uint32_t ah[4];
                ldm_x4(ah, sAh + aoff);
#pragma unroll
                for (int np = 0; np < 4; np++) {
                    mma_f16(acc[mf][2 * np], ah, &bh[np][0]);
                    mma_f16(acc[mf][2 * np + 1], ah, &bh[np][2]);
                }
            }
        }
        __syncthreads();
        if (i + 2 < nch)
            issue_chunk(sb + st * STAGEB, Ah, Bh, lda, ldb,
                        row0, col0, kbeg + i + 2, tid);
        CPA_COMMIT();
    }

    // epilogue
    const int r0 = lane >> 2;
    const int c0 = (lane & 3) * 2;
#pragma unroll
    for (int mf = 0; mf < 4; mf++) {
#pragma unroll
        for (int nf = 0; nf < 8; nf++) {
            const int row = row0 + wm + mf * 16 + r0;
            const int col = col0 + wn + nf * 8 + c0;
            const float x0 = acc[mf][nf][0] * alpha;
            const float x1 = acc[mf][nf][1] * alpha;
            const float x2 = acc[mf][nf][2] * alpha;
            const float x3 = acc[mf][nf][3] * alpha;
            if (omode == 0) {
                *(float2*)(C + (size_t)row * ldc + col)       = make_float2(x0, x1);
                *(float2*)(C + (size_t)(row + 8) * ldc + col) = make_float2(x2, x3);
            } else {
                *(uint32_t*)(Ch + (size_t)row * ldc + col) =
                    (uint32_t)h16(__float2half_rn(x0)) |
                    ((uint32_t)h16(__float2half_rn(x1)) << 16);
                *(uint32_t*)(Ch + (size_t)(row + 8) * ldc + col) =
                    (uint32_t)h16(__float2half_rn(x2)) |
                    ((uint32_t)h16(__float2half_rn(x3)) << 16);
            }
        }
    }
}

// ---------------------------------------------------------------------------
// PV split-K reduce: out = PSCALE_INV * sum_s part[s], fixed order.
// ---------------------------------------------------------------------------
__global__ void __launch_bounds__(256)
reduce_pv(const float* __restrict__ part, float* __restrict__ out)
{
    const size_t i4 = (size_t)blockIdx.x * blockDim.x + threadIdx.x;
    if (i4 >= (size_t)NSEQ * DIM / 4) return;
    const int row = (int)((i4 * 4) / DIM);
    const int nseg = row / 1024 + 1;
    const size_t stride4 = (size_t)NSEQ * DIM / 4;
    float4 a = ((const float4*)part)[i4];
    for (int s = 1; s < nseg; s++) {
        const float4 b = ((const float4*)part)[s * stride4 + i4];
        a.x += b.x; a.y += b.y; a.z += b.z; a.w += b.w;
    }
    a.x *= PSCALE_INV; a.y *= PSCALE_INV; a.z *= PSCALE_INV; a.w *= PSCALE_INV;
    ((float4*)out)[i4] = a;
}

// ---------------------------------------------------------------------------
// batched fp32 -> fp16 convert: z selects input pointer; outputs adjacent
// ---------------------------------------------------------------------------
__global__ void conv_f32_h2(const float* __restrict__ in0,
                            const float* __restrict__ in1,
                            __half* __restrict__ out, size_t n4)
{
    const size_t i = (size_t)blockIdx.x * blockDim.x + threadIdx.x;
    if (i >= n4) return;
    const float* in = blockIdx.y ? in1 : in0;
    const float4 v = ((const float4*)in)[i];
    uint2 H;
    H.x = (uint32_t)h16(__float2half_rn(v.x)) |
          ((uint32_t)h16(__float2half_rn(v.y)) << 16);
    H.y = (uint32_t)h16(__float2half_rn(v.z)) |
          ((uint32_t)h16(__float2half_rn(v.w)) << 16);
    ((uint2*)(out + (size_t)blockIdx.y * n4 * 4))[i] = H;
}

// single-input version (V chain)
__global__ void conv_f32_h(const float* __restrict__ in,
                           __half* __restrict__ out, size_t n4)
{
    const size_t i = (size_t)blockIdx.x * blockDim.x + threadIdx.x;
    if (i >= n4) return;
    const float4 v = ((const float4*)in)[i];
    uint2 H;
    H.x = (uint32_t)h16(__float2half_rn(v.x)) |
          ((uint32_t)h16(__float2half_rn(v.y)) << 16);
    H.y = (uint32_t)h16(__float2half_rn(v.z)) |
          ((uint32_t)h16(__float2half_rn(v.w)) << 16);
    ((uint2*)out)[i] = H;
}

// ---------------------------------------------------------------------------
// batched transpose fp32 -> fp16: z selects input; outputs adjacent (+z*R*C)
// ---------------------------------------------------------------------------
__global__ void transpose_f32_h2(const float* __restrict__ in0,
                                 const float* __restrict__ in1,
                                 __half* __restrict__ out, int R, int C)
{
    __shared__ float t[32][33];
    const float* in = blockIdx.z ? in1 : in0;
    out += (size_t)blockIdx.z * R * C;
    const int bx = blockIdx.x * 32;
    const int by = blockIdx.y * 32;
    const int tx = threadIdx.x;
    for (int j = threadIdx.y; j < 32; j += 8)
        t[j][tx] = in[(size_t)(by + j) * C + bx + tx];
    __syncthreads();
    for (int j = threadIdx.y; j < 32; j += 8)
        out[(size_t)(bx + j) * R + by + tx] = __float2half_rn(t[tx][j]);
}

// single-input version (Wv on side stream)
__global__ void transpose_f32_h(const float* __restrict__ in,
                                __half* __restrict__ out, int R, int C)
{
    __shared__ float t[32][33];
    const int bx = blockIdx.x * 32;
    const int by = blockIdx.y * 32;
    const int tx = threadIdx.x;
    for (int j = threadIdx.y; j < 32; j += 8)
        t[j][tx] = in[(size_t)(by + j) * C + bx + tx];
    __syncthreads();
    for (int j = threadIdx.y; j < 32; j += 8)
        out[(size_t)(bx + j) * R + by + tx] = __float2half_rn(t[tx][j]);
}

// ---------------------------------------------------------------------------
// transpose fp16 -> fp16
// ---------------------------------------------------------------------------
__global__ void transpose_h(const __half* __restrict__ in,
                            __half* __restrict__ out, int R, int C)
{
    __shared__ __half t[32][34];
    const int bx = blockIdx.x * 32;
    const int by = blockIdx.y * 32;
    const int tx = threadIdx.x;
    for (int j = threadIdx.y; j < 32; j += 8)
        t[j][tx] = in[(size_t)(by + j) * C + bx + tx];
    __syncthreads();
    for (int j = threadIdx.y; j < 32; j += 8)
        out[(size_t)(bx + j) * R + by + tx] = t[tx][j];
}

// ---------------------------------------------------------------------------
// single-pass causal row softmax, vectorized I/O: each thread owns 8 groups
// of 4 consecutive cols (float4 loads, uint2 fp16x4 stores). Masked elements
// become exp(-1e30-m)=0, so stores are unconditional up to the 256-pad bound.
// ---------------------------------------------------------------------------
__global__ void __launch_bounds__(256)
softmax1(const float* __restrict__ S, __half* __restrict__ P)
{
    __shared__ float red[8];
    const int row = blockIdx.x;
    const int tid = threadIdx.x;
    const int lane = tid & 31;
    const int wid = tid >> 5;
    const float* srow = S + (size_t)row * NSEQ;
    __half* prow = P + (size_t)row * NSEQ;
    const int n      = row + 1;
    const int padded = (row & ~255) + 256;

    float v[32];
    float m = -1e30f;
#pragma unroll
    for (int i = 0; i < 8; i++) {
        const int c = i * 1024 + tid * 4;
        const float4 s4 = *(const float4*)(srow + c);   // in-bounds (<8192)
        v[4 * i + 0] = (c + 0 < n) ? s4.x : -1e30f;
        v[4 * i + 1] = (c + 1 < n) ? s4.y : -1e30f;
        v[4 * i + 2] = (c + 2 < n) ? s4.z : -1e30f;
        v[4 * i + 3] = (c + 3 < n) ? s4.w : -1e30f;
        m = fmaxf(m, fmaxf(fmaxf(v[4 * i], v[4 * i + 1]),
                           fmaxf(v[4 * i + 2], v[4 * i + 3])));
    }
#pragma unroll
    for (int o = 16; o; o >>= 1) m = fmaxf(m, __shfl_xor_sync(~0u, m, o));
    if (lane == 0) red[wid] = m;
    __syncthreads();
    m = -1e30f;
#pragma unroll
    for (int w = 0; w < 8; w++) m = fmaxf(m, red[w]);
    __syncthreads();

    float sum = 0.f;
#pragma unroll
    for (int i = 0; i < 32; i++) {
        const float e = __expf(v[i] - m);   // -1e30 - m -> 0
        v[i] = e;
        sum += e;
    }
#pragma unroll
    for (int o = 16; o; o >>= 1) sum += __shfl_xor_sync(~0u, sum, o);
    if (lane == 0) red[wid] = sum;
    __syncthreads();
    sum = 0.f;
#pragma unroll
    for (int w = 0; w < 8; w++) sum += red[w];
    const float inv_sc = PSCALE / sum;

#pragma unroll
    for (int i = 0; i < 8; i++) {
        const int c = i * 1024 + tid * 4;
        if (c < padded) {
            uint2 o;
            o.x = (uint32_t)h16(__float2half_rn(v[4 * i + 0] * inv_sc)) |
                  ((uint32_t)h16(__float2half_rn(v[4 * i + 1] * inv_sc)) << 16);
            o.y = (uint32_t)h16(__float2half_rn(v[4 * i + 2] * inv_sc)) |
                  ((uint32_t)h16(__float2half_rn(v[4 * i + 3] * inv_sc)) << 16);
            *(uint2*)(prow + c) = o;
        }
    }
}

// ---------------------------------------------------------------------------
extern "C" void kernel_launch(void* const* d_in, const int* in_sizes, int n_in,
                              void* d_out, int out_size)
{
    const float* q  = (const float*)d_in[0];
    const float* k  = (const float*)d_in[1];
    const float* v  = (const float*)d_in[2];
    const float* Wq = (const float*)d_in[3];
    const float* Wk = (const float*)d_in[4];
    const float* Wv = (const float*)d_in[5];
    float* out = (float*)d_out;

    __half *qk16, *v16, *WT, *QK, *Vr, *VT, *P;
    float *S, *Opart;
    cudaGetSymbolAddress((void**)&qk16, g_qk16);
    cudaGetSymbolAddress((void**)&v16, g_v16);
    cudaGetSymbolAddress((void**)&WT, g_WT);
    cudaGetSymbolAddress((void**)&QK, g_QK);
    cudaGetSymbolAddress((void**)&Vr, g_Vr);
    cudaGetSymbolAddress((void**)&VT, g_VT);
    cudaGetSymbolAddress((void**)&S,  g_S);
    cudaGetSymbolAddress((void**)&P,  g_P);
    cudaGetSymbolAddress((void**)&Opart, g_Opart);

    const size_t WW = (size_t)DIM * DIM;
    const size_t ND = (size_t)NSEQ * DIM;
    __half* q16 = qk16;
    __half* Qh  = QK;
    __half* Kh  = QK + ND;

    cudaFuncSetAttribute(gemm_nt, cudaFuncAttributeMaxDynamicSharedMemorySize,
                         SMEM_GEMM_BYTES);

    const dim3 blk(256);
    const dim3 tblk(32, 8);
    const size_t n4 = ND / 4;
    const unsigned gcv = (unsigned)((n4 + 255) / 256);
    const dim3 gsc(NSEQ / BN, NSEQ / BM);            // (64, 32)
    const dim3 gpv(DIM / BN, NSEQ / BM, NSEG);       // (8, 32, 8) split-K

    // R11/R13's fork-join pattern (passes the teardown check):
    // ONE side stream for the V chain, two events.
    cudaStream_t side;
    cudaStreamCreateWithFlags(&side, cudaStreamNonBlocking);
    cudaEvent_t eFork, eJoin;
    cudaEventCreateWithFlags(&eFork, cudaEventDisableTiming);
    cudaEventCreateWithFlags(&eJoin, cudaEventDisableTiming);

    cudaEventRecord(eFork, 0);
    cudaStreamWaitEvent(side, eFork, 0);

    // ---- side stream: V chain ----
    conv_f32_h<<<gcv, blk, 0, side>>>(v, v16, n4);
    transpose_f32_h<<<dim3(DIM / 32, DIM / 32), tblk, 0, side>>>(
        Wv, WT + 2 * WW, DIM, DIM);
    gemm_nt<<<dim3(DIM / BN, NSEQ / BM), blk, SMEM_GEMM_BYTES, side>>>(
        v16, WT + 2 * WW, nullptr, Vr, DIM, DIM, DIM, 1.0f, DIM / BK,
        0, 2, 0, 0, 0);
    transpose_h<<<dim3(DIM / 32, NSEQ / 32), tblk, 0, side>>>(Vr, VT, NSEQ, DIM);
    cudaEventRecord(eJoin, side);

    // ---- main stream: Q/K chain ----
    conv_f32_h2<<<dim3(gcv, 2), blk>>>(q, k, qk16, n4);
    transpose_f32_h2<<<dim3(DIM / 32, DIM / 32, 2), tblk>>>(Wq, Wk, WT, DIM, DIM);

    // batched Q,K projections: z selects (q16|k16, WTq|WTk, Qh|Kh)
    gemm_nt<<<dim3(DIM / BN, NSEQ / BM, 2), blk, SMEM_GEMM_BYTES>>>(
        q16, WT, nullptr, Qh, DIM, DIM, DIM, 1.0f, DIM / BK,
        0, 2, ND, WW, ND);

    // scores: S = (Q K^T)/sqrt(Dk), causal tile skip
    gemm_nt<<<gsc, blk, SMEM_GEMM_BYTES>>>(
        Qh, Kh, S, nullptr, DIM, DIM, NSEQ, 0.03125f, DIM / BK,
        1, 0, 0, 0, 0);

    // single-pass softmax -> fp16 P (scaled by 4096), vectorized I/O
    softmax1<<<NSEQ, blk>>>(S, P);

    // join: PV needs V^T from the side stream
    cudaStreamWaitEvent(0, eJoin, 0);

    // O = P @ (V^T)^T via split-K (16-chunk segments), partials fp32
    gemm_nt<<<gpv, blk, SMEM_GEMM_BYTES>>>(
        P, VT, Opart, nullptr, NSEQ, NSEQ, DIM, 1.0f, 16,
        3, 0, 0, 0, ND);

    // fixed-order reduce (+ 1/PSCALE)
    reduce_pv<<<gcv, blk>>>(Opart, out);
}

// round 15
// speedup vs baseline: 1.0173x; 1.0173x over previous
#include <cuda_runtime.h>
#include <cuda_fp16.h>
#include <cstdint>

#define NSEQ 8192
#define DIM  1024

// ---------------- scratch (module statics; no runtime allocation) ----------
__device__ __half g_qk16[2][(size_t)NSEQ * DIM];       // q,k fp16 (adjacent)
__device__ __half g_v16[(size_t)NSEQ * DIM];
__device__ __half g_WT[3][(size_t)DIM * DIM];          // Wq^T, Wk^T, Wv^T fp16
__device__ __half g_QK[2][(size_t)NSEQ * DIM];         // Q,K projections (adjacent)
__device__ __half g_Vr[(size_t)NSEQ * DIM];
__device__ __half g_VT[(size_t)DIM * NSEQ];
__device__ float  g_S [(size_t)NSEQ * NSEQ];
__device__ __half g_P [(size_t)NSEQ * NSEQ];
#define NSEG 8
__device__ float  g_Opart[NSEG][(size_t)NSEQ * DIM];   // PV split-K partials

#define PSCALE     4096.0f
#define PSCALE_INV 2.44140625e-4f   // 1/4096, exact

// ---------------- helpers ---------------------------------------------------
__device__ __forceinline__ uint32_t smem_u32(const void* p) {
    uint32_t a;
    asm("{ .reg .u64 t; cvta.to.shared.u64 t, %1; cvt.u32.u64 %0, t; }"
        : "=r"(a) : "l"(p));
    return a;
}
#define SWZ128(off) ((off) ^ (((off) >> 3) & 0x70))

__device__ __forceinline__ void ldm_x4(uint32_t* r, uint32_t addr) {
    asm volatile("ldmatrix.sync.aligned.m8n8.x4.shared.b16 {%0,%1,%2,%3}, [%4];"
                 : "=r"(r[0]), "=r"(r[1]), "=r"(r[2]), "=r"(r[3]) : "r"(addr));
}
__device__ __forceinline__ void mma_f16(float* c, const uint32_t* a,
                                        const uint32_t* b) {
    asm volatile(
        "mma.sync.aligned.m16n8k16.row.col.f32.f16.f16.f32 "
        "{%0,%1,%2,%3}, {%4,%5,%6,%7}, {%8,%9}, {%0,%1,%2,%3};"
        : "+f"(c[0]), "+f"(c[1]), "+f"(c[2]), "+f"(c[3])
        : "r"(a[0]), "r"(a[1]), "r"(a[2]), "r"(a[3]), "r"(b[0]), "r"(b[1]));
}
__device__ __forceinline__ void cpa16(uint32_t dst, const void* src) {
    asm volatile("cp.async.cg.shared.global [%0], [%1], 16;"
                 :: "r"(dst), "l"(src));
}
#define CPA_COMMIT() asm volatile("cp.async.commit_group;" ::: "memory")
#define CPA_WAIT1()  asm volatile("cp.async.wait_group 1;" ::: "memory")

__device__ __forceinline__ uint16_t h16(__half h) {
    return *reinterpret_cast<uint16_t*>(&h);
}

// ---------------------------------------------------------------------------
// 1-term fp16 NT GEMM: C[M,N] = alpha * A[M,K] @ B[N,K]^T, K-major operands.
// CTA 256x128, warp 64x64 (8 warps), BK=64, 2-stage cp.async (96 KB smem).
// cmode: 0 plain; 1 causal tile skip; 3 causal split-K (seg z over kcount
//        chunks, k-limit 4*(by+1), C += z*zsC).
// omode: 0 -> C fp32; 2 -> Ch fp16.
// zsA/zsB/zsC: per-z pointer strides for batched launches (cmode 0).
// ---------------------------------------------------------------------------
#define BM 256
#define BN 128
#define BK 64
#define SLAB_A (BM * BK * 2)               // 32 KB
#define SLAB_B (BN * BK * 2)               // 16 KB
#define STAGEB (SLAB_A + SLAB_B)           // 48 KB
#define SMEM_GEMM_BYTES (2 * STAGEB)       // 96 KB

__device__ __forceinline__ void issue_chunk(
    uint32_t sstage,
    const __half* __restrict__ Ah, const __half* __restrict__ Bh,
    int lda, int ldb, int row0, int col0, int kt, int tid)
{
#pragma unroll
    for (int i = 0; i < 8; i++) {          // A: 2048 16B chunks
        const int idx = i * 256 + tid;
        const int row = idx >> 3, c = idx & 7;
        const uint32_t off = SWZ128((uint32_t)(row * 128 + c * 16));
        const size_t g = (size_t)(row0 + row) * lda + (size_t)kt * BK + c * 8;
        cpa16(sstage + off, Ah + g);
    }
#pragma unroll
    for (int i = 0; i < 4; i++) {          // B: 1024 16B chunks
        const int idx = i * 256 + tid;
        const int row = idx >> 3, c = idx & 7;
        const uint32_t off = SWZ128((uint32_t)(row * 128 + c * 16));
        const size_t g = (size_t)(col0 + row) * ldb + (size_t)kt * BK + c * 8;
        cpa16(sstage + SLAB_A + off, Bh + g);
    }
}

__global__ void __launch_bounds__(256)
gemm_nt(const __half* __restrict__ Ah, const __half* __restrict__ Bh,
        float* __restrict__ C, __half* __restrict__ Ch,
        int lda, int ldb, int ldc, float alpha, int kcount,
        int cmode, int omode, size_t zsA, size_t zsB, size_t zsC)
{
    extern __shared__ char smem[];
    const int tid  = threadIdx.x;
    const int wid  = tid >> 5;
    const int lane = tid & 31;
    const int row0 = blockIdx.y * BM;
    const int col0 = blockIdx.x * BN;
    const int z    = blockIdx.z;

    if (cmode == 1 && col0 >= row0 + BM) return;

    if (zsA) Ah += (size_t)z * zsA;
    if (zsB) Bh += (size_t)z * zsB;

    int kbeg = 0;
    int kend = kcount;
    if (cmode == 3) {
        kbeg = z * kcount;
        const int klim = 4 * (blockIdx.y + 1);
        kend = min(kbeg + kcount, klim);
        if (kbeg >= kend) return;
        C += (size_t)z * zsC;
    } else if (zsC && Ch) {
        Ch += (size_t)z * zsC;
    }
    const int nch = kend - kbeg;

    const int wm = (wid & 3) * 64;
    const int wn = (wid >> 2) * 64;

    float acc[4][8][4];
#pragma unroll
    for (int i = 0; i < 4; i++)
#pragma unroll
        for (int j = 0; j < 8; j++)
#pragma unroll
            for (int r = 0; r < 4; r++) acc[i][j][r] = 0.f;

    const uint32_t sb = smem_u32(smem);

    issue_chunk(sb, Ah, Bh, lda, ldb, row0, col0, kbeg, tid);
    CPA_COMMIT();
    if (nch > 1)
        issue_chunk(sb + STAGEB, Ah, Bh, lda, ldb, row0, col0, kbeg + 1, tid);
    CPA_COMMIT();

    for (int i = 0; i < nch; i++) {
        const int st = i & 1;
        CPA_WAIT1();
        __syncthreads();

        const uint32_t sAh = sb + st * STAGEB;
        const uint32_t sBh = sAh + SLAB_A;

#pragma unroll
        for (int ks = 0; ks < 4; ks++) {
            uint32_t bh[4][4];
#pragma unroll
            for (int np = 0; np < 4; np++) {
                const uint32_t roff = SWZ128((uint32_t)(
                    (wn + np * 16 + ((lane >> 4) << 3) + (lane & 7)) * 128 +
                    ks * 32 + ((lane >> 3) & 1) * 16));
                ldm_x4(bh[np], sBh + roff);
            }
#pragma unroll
            for (int mf = 0; mf < 4; mf++) {
                const uint32_t aoff = SWZ128((uint32_t)(
                    (wm + mf * 16 + (lane & 15)) * 128 +
                    ks * 32 + ((lane >> 4) & 1) * 16));
                uint32_t ah[4];
                ldm_x4(ah, sAh + aoff);
#pragma unroll
                for (int np = 0; np < 4; np++) {
                    mma_f16(acc[mf][2 * np], ah, &bh[np][0]);
                    mma_f16(acc[mf][2 * np + 1], ah, &bh[np][2]);
                }
            }
        }
        __syncthreads();
        if (i + 2 < nch)
            issue_chunk(sb + st * STAGEB, Ah, Bh, lda, ldb,
                        row0, col0, kbeg + i + 2, tid);
        CPA_COMMIT();
    }

    // epilogue
    const int r0 = lane >> 2;
    const int c0 = (lane & 3) * 2;
#pragma unroll
    for (int mf = 0; mf < 4; mf++) {
#pragma unroll
        for (int nf = 0; nf < 8; nf++) {
            const int row = row0 + wm + mf * 16 + r0;
            const int col = col0 + wn + nf * 8 + c0;
            const float x0 = acc[mf][nf][0] * alpha;
            const float x1 = acc[mf][nf][1] * alpha;
            const float x2 = acc[mf][nf][2] * alpha;
            const float x3 = acc[mf][nf][3] * alpha;
            if (omode == 0) {
                *(float2*)(C + (size_t)row * ldc + col)       = make_float2(x0, x1);
                *(float2*)(C + (size_t)(row + 8) * ldc + col) = make_float2(x2, x3);
            } else {
                *(uint32_t*)(Ch + (size_t)row * ldc + col) =
                    (uint32_t)h16(__float2half_rn(x0)) |
                    ((uint32_t)h16(__float2half_rn(x1)) << 16);
                *(uint32_t*)(Ch + (size_t)(row + 8) * ldc + col) =
                    (uint32_t)h16(__float2half_rn(x2)) |
                    ((uint32_t)h16(__float2half_rn(x3)) << 16);
            }
        }
    }
}

// ---------------------------------------------------------------------------
// PV split-K reduce: out = PSCALE_INV * sum_s part[s], fixed order.
// ---------------------------------------------------------------------------
__global__ void __launch_bounds__(256)
reduce_pv(const float* __restrict__ part, float* __restrict__ out)
{
    const size_t i4 = (size_t)blockIdx.x * blockDim.x + threadIdx.x;
    if (i4 >= (size_t)NSEQ * DIM / 4) return;
    const int row = (int)((i4 * 4) / DIM);
    const int nseg = row / 1024 + 1;
    const size_t stride4 = (size_t)NSEQ * DIM / 4;
    float4 a = ((const float4*)part)[i4];
    for (int s = 1; s < nseg; s++) {
        const float4 b = ((const float4*)part)[s * stride4 + i4];
        a.x += b.x; a.y += b.y; a.z += b.z; a.w += b.w;
    }
    a.x *= PSCALE_INV; a.y *= PSCALE_INV; a.z *= PSCALE_INV; a.w *= PSCALE_INV;
    ((float4*)out)[i4] = a;
}

// ---------------------------------------------------------------------------
// fp32 -> fp16 single convert
// ---------------------------------------------------------------------------
__global__ void conv_f32_h(const float* __restrict__ in,
                           __half* __restrict__ out, size_t n4)
{
    const size_t i = (size_t)blockIdx.x * blockDim.x + threadIdx.x;
    if (i >= n4) return;
    const float4 v = ((const float4*)in)[i];
    uint2 H;
    H.x = (uint32_t)h16(__float2half_rn(v.x)) |
          ((uint32_t)h16(__float2half_rn(v.y)) << 16);
    H.y = (uint32_t)h16(__float2half_rn(v.z)) |
          ((uint32_t)h16(__float2half_rn(v.w)) << 16);
    ((uint2*)out)[i] = H;
}

// ---------------------------------------------------------------------------
// transpose fp32 -> fp16 single
// ---------------------------------------------------------------------------
__global__ void transpose_f32_h(const float* __restrict__ in,
                                __half* __restrict__ out, int R, int C)
{
    __shared__ float t[32][33];
    const int bx = blockIdx.x * 32;
    const int by = blockIdx.y * 32;
    const int tx = threadIdx.x;
    for (int j = threadIdx.y; j < 32; j += 8)
        t[j][tx] = in[(size_t)(by + j) * C + bx + tx];
    __syncthreads();
    for (int j = threadIdx.y; j < 32; j += 8)
        out[(size_t)(bx + j) * R + by + tx] = __float2half_rn(t[tx][j]);
}

// ---------------------------------------------------------------------------
// transpose fp16 -> fp16
// ---------------------------------------------------------------------------
__global__ void transpose_h(const __half* __restrict__ in,
                            __half* __restrict__ out, int R, int C)
{
    __shared__ __half t[32][34];
    const int bx = blockIdx.x * 32;
    const int by = blockIdx.y * 32;
    const int tx = threadIdx.x;
    for (int j = threadIdx.y; j < 32; j += 8)
        t[j][tx] = in[(size_t)(by + j) * C + bx + tx];
    __syncthreads();
    for (int j = threadIdx.y; j < 32; j += 8)
        out[(size_t)(bx + j) * R + by + tx] = t[tx][j];
}

// ---------------------------------------------------------------------------
// single-pass causal row softmax: fp32 row in registers, write fp16 P scaled
// by PSCALE, zero-pad to 256-boundary. (R13's scalar version — the R14
// vectorized variant regressed.)
// ---------------------------------------------------------------------------
__global__ void __launch_bounds__(256)
softmax1(const float* __restrict__ S, __half* __restrict__ P)
{
    __shared__ float red[8];
    const int row = blockIdx.x;
    const int tid = threadIdx.x;
    const int lane = tid & 31;
    const int wid = tid >> 5;
    const float* srow = S + (size_t)row * NSEQ;
    __half* prow = P + (size_t)row * NSEQ;
    const int n      = row + 1;
    const int padded = (row & ~255) + 256;

    float v[32];
    float m = -1e30f;
#pragma unroll
    for (int i = 0; i < 32; i++) {
        const int c = i * 256 + tid;
        v[i] = (c < n) ? srow[c] : -1e30f;
        m = fmaxf(m, v[i]);
    }
#pragma unroll
    for (int o = 16; o; o >>= 1) m = fmaxf(m, __shfl_xor_sync(~0u, m, o));
    if (lane == 0) red[wid] = m;
    __syncthreads();
    m = -1e30f;
#pragma unroll
    for (int w = 0; w < 8; w++) m = fmaxf(m, red[w]);
    __syncthreads();

    float sum = 0.f;
#pragma unroll
    for (int i = 0; i < 32; i++) {
        const float e = __expf(v[i] - m);
        v[i] = e;
        sum += e;
    }
#pragma unroll
    for (int o = 16; o; o >>= 1) sum += __shfl_xor_sync(~0u, sum, o);
    if (lane == 0) red[wid] = sum;
    __syncthreads();
    sum = 0.f;
#pragma unroll
    for (int w = 0; w < 8; w++) sum += red[w];
    const float inv_sc = PSCALE / sum;

#pragma unroll
    for (int i = 0; i < 32; i++) {
        const int c = i * 256 + tid;
        if (c < padded) prow[c] = __float2half_rn(v[i] * inv_sc);
    }
}

// ---------------------------------------------------------------------------
extern "C" void kernel_launch(void* const* d_in, const int* in_sizes, int n_in,
                              void* d_out, int out_size)
{
    const float* q  = (const float*)d_in[0];
    const float* k  = (const float*)d_in[1];
    const float* v  = (const float*)d_in[2];
    const float* Wq = (const float*)d_in[3];
    const float* Wk = (const float*)d_in[4];
    const float* Wv = (const float*)d_in[5];
    float* out = (float*)d_out;

    __half *qk16, *v16, *WT, *QK, *Vr, *VT, *P;
    float *S, *Opart;
    cudaGetSymbolAddress((void**)&qk16, g_qk16);
    cudaGetSymbolAddress((void**)&v16, g_v16);
    cudaGetSymbolAddress((void**)&WT, g_WT);
    cudaGetSymbolAddress((void**)&QK, g_QK);
    cudaGetSymbolAddress((void**)&Vr, g_Vr);
    cudaGetSymbolAddress((void**)&VT, g_VT);
    cudaGetSymbolAddress((void**)&S,  g_S);
    cudaGetSymbolAddress((void**)&P,  g_P);
    cudaGetSymbolAddress((void**)&Opart, g_Opart);

    const size_t WW = (size_t)DIM * DIM;
    const size_t ND = (size_t)NSEQ * DIM;
    __half* q16 = qk16;
    __half* k16 = qk16 + ND;
    __half* Qh  = QK;
    __half* Kh  = QK + ND;

    cudaFuncSetAttribute(gemm_nt, cudaFuncAttributeMaxDynamicSharedMemorySize,
                         SMEM_GEMM_BYTES);

    const dim3 blk(256);
    const dim3 tblk(32, 8);
    const size_t n4 = ND / 4;
    const unsigned gcv = (unsigned)((n4 + 255) / 256);
    const dim3 gsc(NSEQ / BN, NSEQ / BM);            // (64, 32)
    const dim3 gpv(DIM / BN, NSEQ / BM, NSEG);       // (8, 32, 8) split-K

    // R13's fork-join (passes teardown): ONE side stream, two events.
    // Program order changed ONLY so the scores GEMM is launch #6 for ncu;
    // the event graph (and thus execution) is identical to R13.
    cudaStream_t side;
    cudaStreamCreateWithFlags(&side, cudaStreamNonBlocking);
    cudaEvent_t eFork, eJoin;
    cudaEventCreateWithFlags(&eFork, cudaEventDisableTiming);
    cudaEventCreateWithFlags(&eJoin, cudaEventDisableTiming);

    cudaEventRecord(eFork, 0);
    cudaStreamWaitEvent(side, eFork, 0);

    // ---- main stream: Q/K chain (launches 1-6) ----
    conv_f32_h<<<gcv, blk>>>(q, q16, n4);                               // 1
    conv_f32_h<<<gcv, blk>>>(k, k16, n4);                               // 2
    transpose_f32_h<<<dim3(DIM / 32, DIM / 32), tblk>>>(Wq, WT, DIM, DIM);      // 3
    transpose_f32_h<<<dim3(DIM / 32, DIM / 32), tblk>>>(Wk, WT + WW, DIM, DIM); // 4

    // 5: batched Q,K projections: z selects (q16|k16, WTq|WTk, Qh|Kh)
    gemm_nt<<<dim3(DIM / BN, NSEQ / BM, 2), blk, SMEM_GEMM_BYTES>>>(
        q16, WT, nullptr, Qh, DIM, DIM, DIM, 1.0f, DIM / BK,
        0, 2, ND, WW, ND);

    // 6: scores: S = (Q K^T)/sqrt(Dk), causal tile skip   <- ncu target
    gemm_nt<<<gsc, blk, SMEM_GEMM_BYTES>>>(
        Qh, Kh, S, nullptr, DIM, DIM, NSEQ, 0.03125f, DIM / BK,
        1, 0, 0, 0, 0);

    // ---- side stream: V chain (enqueued later; executes from eFork) ----
    conv_f32_h<<<gcv, blk, 0, side>>>(v, v16, n4);
    transpose_f32_h<<<dim3(DIM / 32, DIM / 32), tblk, 0, side>>>(
        Wv, WT + 2 * WW, DIM, DIM);
    gemm_nt<<<dim3(DIM / BN, NSEQ / BM), blk, SMEM_GEMM_BYTES, side>>>(
        v16, WT + 2 * WW, nullptr, Vr, DIM, DIM, DIM, 1.0f, DIM / BK,
        0, 2, 0, 0, 0);
    transpose_h<<<dim3(DIM / 32, NSEQ / 32), tblk, 0, side>>>(Vr, VT, NSEQ, DIM);
    cudaEventRecord(eJoin, side);

    // ---- main stream: softmax, PV, reduce ----
    softmax1<<<NSEQ, blk>>>(S, P);

    // join: PV needs V^T from the side stream
    cudaStreamWaitEvent(0, eJoin, 0);

    // O = P @ (V^T)^T via split-K (16-chunk segments), partials fp32
    gemm_nt<<<gpv, blk, SMEM_GEMM_BYTES>>>(
        P, VT, Opart, nullptr, NSEQ, NSEQ, DIM, 1.0f, 16,
        3, 0, 0, 0, ND);

    // fixed-order reduce (+ 1/PSCALE)
    reduce_pv<<<gcv, blk>>>(Opart, out);
}

// round 16
// speedup vs baseline: 1.1296x; 1.1104x over previous
#include <cuda_runtime.h>
#include <cuda_fp16.h>
#include <cstdint>

#define NSEQ 8192
#define DIM  1024

// ---------------- scratch (module statics; no runtime allocation) ----------
__device__ __half g_qk16[2][(size_t)NSEQ * DIM];       // q,k fp16 (adjacent)
__device__ __half g_v16[(size_t)NSEQ * DIM];
__device__ __half g_WT[3][(size_t)DIM * DIM];          // Wq^T, Wk^T, Wv^T fp16
__device__ __half g_QK[2][(size_t)NSEQ * DIM];         // Q,K projections (adjacent)
__device__ __half g_Vr[(size_t)NSEQ * DIM];
__device__ __half g_VT[(size_t)DIM * NSEQ];
__device__ float  g_S [(size_t)NSEQ * NSEQ];
__device__ __half g_P [(size_t)NSEQ * NSEQ];
#define NSEG 8
__device__ float  g_Opart[NSEG][(size_t)NSEQ * DIM];   // PV split-K partials

#define PSCALE     4096.0f
#define PSCALE_INV 2.44140625e-4f   // 1/4096, exact

// ---------------- helpers ---------------------------------------------------
__device__ __forceinline__ uint32_t smem_u32(const void* p) {
    uint32_t a;
    asm("{ .reg .u64 t; cvta.to.shared.u64 t, %1; cvt.u32.u64 %0, t; }"
        : "=r"(a) : "l"(p));
    return a;
}
#define SWZ128(off) ((off) ^ (((off) >> 3) & 0x70))

__device__ __forceinline__ void ldm_x4(uint32_t* r, uint32_t addr) {
    asm volatile("ldmatrix.sync.aligned.m8n8.x4.shared.b16 {%0,%1,%2,%3}, [%4];"
                 : "=r"(r[0]), "=r"(r[1]), "=r"(r[2]), "=r"(r[3]) : "r"(addr));
}
__device__ __forceinline__ void mma_f16(float* c, const uint32_t* a,
                                        const uint32_t* b) {
    asm volatile(
        "mma.sync.aligned.m16n8k16.row.col.f32.f16.f16.f32 "
        "{%0,%1,%2,%3}, {%4,%5,%6,%7}, {%8,%9}, {%0,%1,%2,%3};"
        : "+f"(c[0]), "+f"(c[1]), "+f"(c[2]), "+f"(c[3])
        : "r"(a[0]), "r"(a[1]), "r"(a[2]), "r"(a[3]), "r"(b[0]), "r"(b[1]));
}
__device__ __forceinline__ void cpa16(uint32_t dst, const void* src) {
    asm volatile("cp.async.cg.shared.global [%0], [%1], 16;"
                 :: "r"(dst), "l"(src));
}
#define CPA_COMMIT() asm volatile("cp.async.commit_group;" ::: "memory")
#define CPA_WAIT1()  asm volatile("cp.async.wait_group 1;" ::: "memory")

__device__ __forceinline__ uint16_t h16(__half h) {
    return *reinterpret_cast<uint16_t*>(&h);
}

// ---------------------------------------------------------------------------
// 1-term fp16 NT GEMM: C[M,N] = alpha * A[M,K] @ B[N,K]^T, K-major operands.
// CTA 128x128, warp 32x64 (8 warps: 4 in M, 2 in N), BK=64, 2-stage cp.async
// (64 KB smem). __launch_bounds__(256, 2) forces regs<=128 -> 2 CTAs/SM:
// co-resident CTAs cover each other's sync/wait stalls.
// cmode: 0 plain; 1 causal tile skip; 3 causal split-K (seg z over kcount
//        chunks, k-limit (row0+BM)/BK, C += z*zsC).
// omode: 0 -> C fp32; 2 -> Ch fp16.
// zsA/zsB/zsC: per-z pointer strides for batched launches (cmode 0).
// Per-element k accumulation order identical to the 256x128 version.
// ---------------------------------------------------------------------------
#define BM 128
#define BN 128
#define BK 64
#define SLAB_A (BM * BK * 2)               // 16 KB
#define SLAB_B (BN * BK * 2)               // 16 KB
#define STAGEB (SLAB_A + SLAB_B)           // 32 KB
#define SMEM_GEMM_BYTES (2 * STAGEB)       // 64 KB

__device__ __forceinline__ void issue_chunk(
    uint32_t sstage,
    const __half* __restrict__ Ah, const __half* __restrict__ Bh,
    int lda, int ldb, int row0, int col0, int kt, int tid)
{
#pragma unroll
    for (int i = 0; i < 4; i++) {          // A: 1024 16B chunks
        const int idx = i * 256 + tid;
        const int row = idx >> 3, c = idx & 7;
        const uint32_t off = SWZ128((uint32_t)(row * 128 + c * 16));
        const size_t g = (size_t)(row0 + row) * lda + (size_t)kt * BK + c * 8;
        cpa16(sstage + off, Ah + g);
    }
#pragma unroll
    for (int i = 0; i < 4; i++) {          // B: 1024 16B chunks
        const int idx = i * 256 + tid;
        const int row = idx >> 3, c = idx & 7;
        const uint32_t off = SWZ128((uint32_t)(row * 128 + c * 16));
        const size_t g = (size_t)(col0 + row) * ldb + (size_t)kt * BK + c * 8;
        cpa16(sstage + SLAB_A + off, Bh + g);
    }
}

__global__ void __launch_bounds__(256, 2)
gemm_nt(const __half* __restrict__ Ah, const __half* __restrict__ Bh,
        float* __restrict__ C, __half* __restrict__ Ch,
        int lda, int ldb, int ldc, float alpha, int kcount,
        int cmode, int omode, size_t zsA, size_t zsB, size_t zsC)
{
    extern __shared__ char smem[];
    const int tid  = threadIdx.x;
    const int wid  = tid >> 5;
    const int lane = tid & 31;
    const int row0 = blockIdx.y * BM;
    const int col0 = blockIdx.x * BN;
    const int z    = blockIdx.z;

    if (cmode == 1 && col0 >= row0 + BM) return;

    if (zsA) Ah += (size_t)z * zsA;
    if (zsB) Bh += (size_t)z * zsB;

    int kbeg = 0;
    int kend = kcount;
    if (cmode == 3) {
        kbeg = z * kcount;
        const int klim = (row0 + BM) / BK;
        kend = min(kbeg + kcount, klim);
        if (kbeg >= kend) return;
        C += (size_t)z * zsC;
    } else if (zsC && Ch) {
        Ch += (size_t)z * zsC;
    }
    const int nch = kend - kbeg;

    const int wm = (wid & 3) * 32;     // 4 warps in M, 32 rows each
    const int wn = (wid >> 2) * 64;    // 2 warps in N, 64 cols each

    float acc[2][8][4];
#pragma unroll
    for (int i = 0; i < 2; i++)
#pragma unroll
        for (int j = 0; j < 8; j++)
#pragma unroll
            for (int r = 0; r < 4; r++) acc[i][j][r] = 0.f;

    const uint32_t sb = smem_u32(smem);

    issue_chunk(sb, Ah, Bh, lda, ldb, row0, col0, kbeg, tid);
    CPA_COMMIT();
    if (nch > 1)
        issue_chunk(sb + STAGEB, Ah, Bh, lda, ldb, row0, col0, kbeg + 1, tid);
    CPA_COMMIT();

    for (int i = 0; i < nch; i++) {
        const int st = i & 1;
        CPA_WAIT1();
        __syncthreads();

        const uint32_t sAh = sb + st * STAGEB;
        const uint32_t sBh = sAh + SLAB_A;

#pragma unroll
        for (int ks = 0; ks < 4; ks++) {
            uint32_t bh[4][4];
#pragma unroll
            for (int np = 0; np < 4; np++) {
                const uint32_t roff = SWZ128((uint32_t)(
                    (wn + np * 16 + ((lane >> 4) << 3) + (lane & 7)) * 128 +
                    ks * 32 + ((lane >> 3) & 1) * 16));
                ldm_x4(bh[np], sBh + roff);
            }
#pragma unroll
            for (int mf = 0; mf < 2; mf++) {
                const uint32_t aoff = SWZ128((uint32_t)(
                    (wm + mf * 16 + (lane & 15)) * 128 +
                    ks * 32 + ((lane >> 4) & 1) * 16));
                uint32_t ah[4];
                ldm_x4(ah, sAh + aoff);
#pragma unroll
                for (int np = 0; np < 4; np++) {
                    mma_f16(acc[mf][2 * np], ah, &bh[np][0]);
                    mma_f16(acc[mf][2 * np + 1], ah, &bh[np][2]);
                }
            }
        }
        __syncthreads();
        if (i + 2 < nch)
            issue_chunk(sb + st * STAGEB, Ah, Bh, lda, ldb,
                        row0, col0, kbeg + i + 2, tid);
        CPA_COMMIT();
    }

    // epilogue
    const int r0 = lane >> 2;
    const int c0 = (lane & 3) * 2;
#pragma unroll
    for (int mf = 0; mf < 2; mf++) {
#pragma unroll
        for (int nf = 0; nf < 8; nf++) {
            const int row = row0 + wm + mf * 16 + r0;
            const int col = col0 + wn + nf * 8 + c0;
            const float x0 = acc[mf][nf][0] * alpha;
            const float x1 = acc[mf][nf][1] * alpha;
            const float x2 = acc[mf][nf][2] * alpha;
            const float x3 = acc[mf][nf][3] * alpha;
            if (omode == 0) {
                *(float2*)(C + (size_t)row * ldc + col)       = make_float2(x0, x1);
                *(float2*)(C + (size_t)(row + 8) * ldc + col) = make_float2(x2, x3);
            } else {
                *(uint32_t*)(Ch + (size_t)row * ldc + col) =
                    (uint32_t)h16(__float2half_rn(x0)) |
                    ((uint32_t)h16(__float2half_rn(x1)) << 16);
                *(uint32_t*)(Ch + (size_t)(row + 8) * ldc + col) =
                    (uint32_t)h16(__float2half_rn(x2)) |
                    ((uint32_t)h16(__float2half_rn(x3)) << 16);
            }
        }
    }
}

// ---------------------------------------------------------------------------
// PV split-K reduce: out = PSCALE_INV * sum_s part[s], fixed order.
// (segment still covers 1024 k-elements; unchanged)
// ---------------------------------------------------------------------------
__global__ void __launch_bounds__(256)
reduce_pv(const float* __restrict__ part, float* __restrict__ out)
{
    const size_t i4 = (size_t)blockIdx.x * blockDim.x + threadIdx.x;
    if (i4 >= (size_t)NSEQ * DIM / 4) return;
    const int row = (int)((i4 * 4) / DIM);
    const int nseg = row / 1024 + 1;
    const size_t stride4 = (size_t)NSEQ * DIM / 4;
    float4 a = ((const float4*)part)[i4];
    for (int s = 1; s < nseg; s++) {
        const float4 b = ((const float4*)part)[s * stride4 + i4];
        a.x += b.x; a.y += b.y; a.z += b.z; a.w += b.w;
    }
    a.x *= PSCALE_INV; a.y *= PSCALE_INV; a.z *= PSCALE_INV; a.w *= PSCALE_INV;
    ((float4*)out)[i4] = a;
}

// ---------------------------------------------------------------------------
// fp32 -> fp16 single convert
// ---------------------------------------------------------------------------
__global__ void conv_f32_h(const float* __restrict__ in,
                           __half* __restrict__ out, size_t n4)
{
    const size_t i = (size_t)blockIdx.x * blockDim.x + threadIdx.x;
    if (i >= n4) return;
    const float4 v = ((const float4*)in)[i];
    uint2 H;
    H.x = (uint32_t)h16(__float2half_rn(v.x)) |
          ((uint32_t)h16(__float2half_rn(v.y)) << 16);
    H.y = (uint32_t)h16(__float2half_rn(v.z)) |
          ((uint32_t)h16(__float2half_rn(v.w)) << 16);
    ((uint2*)out)[i] = H;
}

// ---------------------------------------------------------------------------
// transpose fp32 -> fp16 single
// ---------------------------------------------------------------------------
__global__ void transpose_f32_h(const float* __restrict__ in,
                                __half* __restrict__ out, int R, int C)
{
    __shared__ float t[32][33];
    const int bx = blockIdx.x * 32;
    const int by = blockIdx.y * 32;
    const int tx = threadIdx.x;
    for (int j = threadIdx.y; j < 32; j += 8)
        t[j][tx] = in[(size_t)(by + j) * C + bx + tx];
    __syncthreads();
    for (int j = threadIdx.y; j < 32; j += 8)
        out[(size_t)(bx + j) * R + by + tx] = __float2half_rn(t[tx][j]);
}

// ---------------------------------------------------------------------------
// transpose fp16 -> fp16
// ---------------------------------------------------------------------------
__global__ void transpose_h(const __half* __restrict__ in,
                            __half* __restrict__ out, int R, int C)
{
    __shared__ __half t[32][34];
    const int bx = blockIdx.x * 32;
    const int by = blockIdx.y * 32;
    const int tx = threadIdx.x;
    for (int j = threadIdx.y; j < 32; j += 8)
        t[j][tx] = in[(size_t)(by + j) * C + bx + tx];
    __syncthreads();
    for (int j = threadIdx.y; j < 32; j += 8)
        out[(size_t)(bx + j) * R + by + tx] = t[tx][j];
}

// ---------------------------------------------------------------------------
// single-pass causal row softmax: fp32 row in registers, write fp16 P scaled
// by PSCALE, zero-pad to 256-boundary.
// ---------------------------------------------------------------------------
__global__ void __launch_bounds__(256)
softmax1(const float* __restrict__ S, __half* __restrict__ P)
{
    __shared__ float red[8];
    const int row = blockIdx.x;
    const int tid = threadIdx.x;
    const int lane = tid & 31;
    const int wid = tid >> 5;
    const float* srow = S + (size_t)row * NSEQ;
    __half* prow = P + (size_t)row * NSEQ;
    const int n      = row + 1;
    const int padded = (row & ~255) + 256;

    float v[32];
    float m = -1e30f;
#pragma unroll
    for (int i = 0; i < 32; i++) {
        const int c = i * 256 + tid;
        v[i] = (c < n) ? srow[c] : -1e30f;
        m = fmaxf(m, v[i]);
    }
#pragma unroll
    for (int o = 16; o; o >>= 1) m = fmaxf(m, __shfl_xor_sync(~0u, m, o));
    if (lane == 0) red[wid] = m;
    __syncthreads();
    m = -1e30f;
#pragma unroll
    for (int w = 0; w < 8; w++) m = fmaxf(m, red[w]);
    __syncthreads();

    float sum = 0.f;
#pragma unroll
    for (int i = 0; i < 32; i++) {
        const float e = __expf(v[i] - m);
        v[i] = e;
        sum += e;
    }
#pragma unroll
    for (int o = 16; o; o >>= 1) sum += __shfl_xor_sync(~0u, sum, o);
    if (lane == 0) red[wid] = sum;
    __syncthreads();
    sum = 0.f;
#pragma unroll
    for (int w = 0; w < 8; w++) sum += red[w];
    const float inv_sc = PSCALE / sum;

#pragma unroll
    for (int i = 0; i < 32; i++) {
        const int c = i * 256 + tid;
        if (c < padded) prow[c] = __float2half_rn(v[i] * inv_sc);
    }
}

// ---------------------------------------------------------------------------
extern "C" void kernel_launch(void* const* d_in, const int* in_sizes, int n_in,
                              void* d_out, int out_size)
{
    const float* q  = (const float*)d_in[0];
    const float* k  = (const float*)d_in[1];
    const float* v  = (const float*)d_in[2];
    const float* Wq = (const float*)d_in[3];
    const float* Wk = (const float*)d_in[4];
    const float* Wv = (const float*)d_in[5];
    float* out = (float*)d_out;

    __half *qk16, *v16, *WT, *QK, *Vr, *VT, *P;
    float *S, *Opart;
    cudaGetSymbolAddress((void**)&qk16, g_qk16);
    cudaGetSymbolAddress((void**)&v16, g_v16);
    cudaGetSymbolAddress((void**)&WT, g_WT);
    cudaGetSymbolAddress((void**)&QK, g_QK);
    cudaGetSymbolAddress((void**)&Vr, g_Vr);
    cudaGetSymbolAddress((void**)&VT, g_VT);
    cudaGetSymbolAddress((void**)&S,  g_S);
    cudaGetSymbolAddress((void**)&P,  g_P);
    cudaGetSymbolAddress((void**)&Opart, g_Opart);

    const size_t WW = (size_t)DIM * DIM;
    const size_t ND = (size_t)NSEQ * DIM;
    __half* q16 = qk16;
    __half* k16 = qk16 + ND;
    __half* Qh  = QK;
    __half* Kh  = QK + ND;

    cudaFuncSetAttribute(gemm_nt, cudaFuncAttributeMaxDynamicSharedMemorySize,
                         SMEM_GEMM_BYTES);

    const dim3 blk(256);
    const dim3 tblk(32, 8);
    const size_t n4 = ND / 4;
    const unsigned gcv = (unsigned)((n4 + 255) / 256);
    const dim3 gproj(DIM / BN, NSEQ / BM, 2);        // (8, 64, 2)
    const dim3 gsc(NSEQ / BN, NSEQ / BM);            // (64, 64)
    const dim3 gpv(DIM / BN, NSEQ / BM, NSEG);       // (8, 64, 8) split-K

    // R13's fork-join (passes teardown): ONE side stream, two events.
    cudaStream_t side;
    cudaStreamCreateWithFlags(&side, cudaStreamNonBlocking);
    cudaEvent_t eFork, eJoin;
    cudaEventCreateWithFlags(&eFork, cudaEventDisableTiming);
    cudaEventCreateWithFlags(&eJoin, cudaEventDisableTiming);

    cudaEventRecord(eFork, 0);
    cudaStreamWaitEvent(side, eFork, 0);

    // ---- side stream: V chain ----
    conv_f32_h<<<gcv, blk, 0, side>>>(v, v16, n4);
    transpose_f32_h<<<dim3(DIM / 32, DIM / 32), tblk, 0, side>>>(
        Wv, WT + 2 * WW, DIM, DIM);
    gemm_nt<<<dim3(DIM / BN, NSEQ / BM), blk, SMEM_GEMM_BYTES, side>>>(
        v16, WT + 2 * WW, nullptr, Vr, DIM, DIM, DIM, 1.0f, DIM / BK,
        0, 2, 0, 0, 0);
    transpose_h<<<dim3(DIM / 32, NSEQ / 32), tblk, 0, side>>>(Vr, VT, NSEQ, DIM);
    cudaEventRecord(eJoin, side);

    // ---- main stream: Q/K chain ----
    conv_f32_h<<<gcv, blk>>>(q, q16, n4);
    conv_f32_h<<<gcv, blk>>>(k, k16, n4);
    transpose_f32_h<<<dim3(DIM / 32, DIM / 32), tblk>>>(Wq, WT, DIM, DIM);
    transpose_f32_h<<<dim3(DIM / 32, DIM / 32), tblk>>>(Wk, WT + WW, DIM, DIM);

    // batched Q,K projections: z selects (q16|k16, WTq|WTk, Qh|Kh)
    gemm_nt<<<gproj, blk, SMEM_GEMM_BYTES>>>(
        q16, WT, nullptr, Qh, DIM, DIM, DIM, 1.0f, DIM / BK,
        0, 2, ND, WW, ND);

    // scores: S = (Q K^T)/sqrt(Dk), causal tile skip
    gemm_nt<<<gsc, blk, SMEM_GEMM_BYTES>>>(
        Qh, Kh, S, nullptr, DIM, DIM, NSEQ, 0.03125f, DIM / BK,
        1, 0, 0, 0, 0);

    // single-pass softmax -> fp16 P (scaled by 4096)
    softmax1<<<NSEQ, blk>>>(S, P);

    // join: PV needs V^T from the side stream
    cudaStreamWaitEvent(0, eJoin, 0);

    // O = P @ (V^T)^T via split-K (16-chunk segments), partials fp32
    gemm_nt<<<gpv, blk, SMEM_GEMM_BYTES>>>(
        P, VT, Opart, nullptr, NSEQ, NSEQ, DIM, 1.0f, 16,
        3, 0, 0, 0, ND);

    // fixed-order reduce (+ 1/PSCALE)
    reduce_pv<<<gcv, blk>>>(Opart, out);
}

// round 17
// speedup vs baseline: 1.1454x; 1.0140x over previous
#include <cuda_runtime.h>
#include <cuda_fp16.h>
#include <cstdint>

#define NSEQ 8192
#define DIM  1024

// ---------------- scratch (module statics; no runtime allocation) ----------
__device__ __half g_qk16[2][(size_t)NSEQ * DIM];       // q,k fp16 (adjacent)
__device__ __half g_v16[(size_t)NSEQ * DIM];
__device__ __half g_WT[3][(size_t)DIM * DIM];          // Wq^T, Wk^T, Wv^T fp16
__device__ __half g_QK[2][(size_t)NSEQ * DIM];         // Q,K projections (adjacent)
__device__ __half g_Vr[(size_t)NSEQ * DIM];
__device__ __half g_VT[(size_t)DIM * NSEQ];
__device__ float  g_S [(size_t)NSEQ * NSEQ];
__device__ __half g_P [(size_t)NSEQ * NSEQ];
#define NSEG 8
__device__ float  g_Opart[NSEG][(size_t)NSEQ * DIM];   // PV split-K partials

#define PSCALE     4096.0f
#define PSCALE_INV 2.44140625e-4f   // 1/4096, exact

// ---------------- helpers ---------------------------------------------------
__device__ __forceinline__ uint32_t smem_u32(const void* p) {
    uint32_t a;
    asm("{ .reg .u64 t; cvta.to.shared.u64 t, %1; cvt.u32.u64 %0, t; }"
        : "=r"(a) : "l"(p));
    return a;
}
#define SWZ128(off) ((off) ^ (((off) >> 3) & 0x70))

__device__ __forceinline__ void ldm_x4(uint32_t* r, uint32_t addr) {
    asm volatile("ldmatrix.sync.aligned.m8n8.x4.shared.b16 {%0,%1,%2,%3}, [%4];"
                 : "=r"(r[0]), "=r"(r[1]), "=r"(r[2]), "=r"(r[3]) : "r"(addr));
}
__device__ __forceinline__ void mma_f16(float* c, const uint32_t* a,
                                        const uint32_t* b) {
    asm volatile(
        "mma.sync.aligned.m16n8k16.row.col.f32.f16.f16.f32 "
        "{%0,%1,%2,%3}, {%4,%5,%6,%7}, {%8,%9}, {%0,%1,%2,%3};"
        : "+f"(c[0]), "+f"(c[1]), "+f"(c[2]), "+f"(c[3])
        : "r"(a[0]), "r"(a[1]), "r"(a[2]), "r"(a[3]), "r"(b[0]), "r"(b[1]));
}
__device__ __forceinline__ void cpa16(uint32_t dst, const void* src) {
    asm volatile("cp.async.cg.shared.global [%0], [%1], 16;"
                 :: "r"(dst), "l"(src));
}
#define CPA_COMMIT() asm volatile("cp.async.commit_group;" ::: "memory")
#define CPA_WAIT1()  asm volatile("cp.async.wait_group 1;" ::: "memory")

__device__ __forceinline__ uint16_t h16(__half h) {
    return *reinterpret_cast<uint16_t*>(&h);
}

// ---------------------------------------------------------------------------
// 1-term fp16 NT GEMM: C[M,N] = alpha * A[M,K] @ B[N,K]^T, K-major operands.
// CTA 128x128, warp 32x64 (8 warps: 4 in M, 2 in N), BK=64.
// 3-stage cp.async ring (96 KB smem/CTA), __launch_bounds__(256, 2) ->
// 2 CTAs/SM (192 KB smem/SM, 64K regs). Issue-before-compute in the loop.
// cmode: 0 plain; 1 causal tile skip; 3 causal split-K (seg z over kcount
//        chunks, k-limit (row0+BM)/BK, C += z*zsC).
// omode: 0 -> C fp32; 2 -> Ch fp16.
// zsA/zsB/zsC: per-z pointer strides for batched launches (cmode 0).
// Per-element k accumulation order identical to previous rounds.
// ---------------------------------------------------------------------------
#define BM 128
#define BN 128
#define BK 64
#define SLAB_A (BM * BK * 2)               // 16 KB
#define SLAB_B (BN * BK * 2)               // 16 KB
#define STAGEB (SLAB_A + SLAB_B)           // 32 KB
#define NSTAGE 3
#define SMEM_GEMM_BYTES (NSTAGE * STAGEB)  // 96 KB

__device__ __forceinline__ void issue_chunk(
    uint32_t sstage,
    const __half* __restrict__ Ah, const __half* __restrict__ Bh,
    int lda, int ldb, int row0, int col0, int kt, int tid)
{
#pragma unroll
    for (int i = 0; i < 4; i++) {          // A: 1024 16B chunks
        const int idx = i * 256 + tid;
        const int row = idx >> 3, c = idx & 7;
        const uint32_t off = SWZ128((uint32_t)(row * 128 + c * 16));
        const size_t g = (size_t)(row0 + row) * lda + (size_t)kt * BK + c * 8;
        cpa16(sstage + off, Ah + g);
    }
#pragma unroll
    for (int i = 0; i < 4; i++) {          // B: 1024 16B chunks
        const int idx = i * 256 + tid;
        const int row = idx >> 3, c = idx & 7;
        const uint32_t off = SWZ128((uint32_t)(row * 128 + c * 16));
        const size_t g = (size_t)(col0 + row) * ldb + (size_t)kt * BK + c * 8;
        cpa16(sstage + SLAB_A + off, Bh + g);
    }
}

__global__ void __launch_bounds__(256, 2)
gemm_nt(const __half* __restrict__ Ah, const __half* __restrict__ Bh,
        float* __restrict__ C, __half* __restrict__ Ch,
        int lda, int ldb, int ldc, float alpha, int kcount,
        int cmode, int omode, size_t zsA, size_t zsB, size_t zsC)
{
    extern __shared__ char smem[];
    const int tid  = threadIdx.x;
    const int wid  = tid >> 5;
    const int lane = tid & 31;
    const int row0 = blockIdx.y * BM;
    const int col0 = blockIdx.x * BN;
    const int z    = blockIdx.z;

    if (cmode == 1 && col0 >= row0 + BM) return;

    if (zsA) Ah += (size_t)z * zsA;
    if (zsB) Bh += (size_t)z * zsB;

    int kbeg = 0;
    int kend = kcount;
    if (cmode == 3) {
        kbeg = z * kcount;
        const int klim = (row0 + BM) / BK;
        kend = min(kbeg + kcount, klim);
        if (kbeg >= kend) return;
        C += (size_t)z * zsC;
    } else if (zsC && Ch) {
        Ch += (size_t)z * zsC;
    }
    const int nch = kend - kbeg;

    const int wm = (wid & 3) * 32;     // 4 warps in M, 32 rows each
    const int wn = (wid >> 2) * 64;    // 2 warps in N, 64 cols each

    float acc[2][8][4];
#pragma unroll
    for (int i = 0; i < 2; i++)
#pragma unroll
        for (int j = 0; j < 8; j++)
#pragma unroll
            for (int r = 0; r < 4; r++) acc[i][j][r] = 0.f;

    const uint32_t sb = smem_u32(smem);

    // prologue: chunks kbeg, kbeg+1 into stages 0, 1 (one group each)
    issue_chunk(sb, Ah, Bh, lda, ldb, row0, col0, kbeg, tid);
    CPA_COMMIT();
    if (nch > 1)
        issue_chunk(sb + STAGEB, Ah, Bh, lda, ldb, row0, col0, kbeg + 1, tid);
    CPA_COMMIT();

    int st = 0;                        // stage of chunk i
    int si = 2;                        // stage for chunk i+2
    for (int i = 0; i < nch; i++) {
        CPA_WAIT1();                   // chunk i's group complete
        __syncthreads();               // data visible; stage si free (consumed i-1)

        if (i + 2 < nch)
            issue_chunk(sb + si * STAGEB, Ah, Bh, lda, ldb,
                        row0, col0, kbeg + i + 2, tid);
        CPA_COMMIT();                  // unconditional: exact group count

        const uint32_t sAh = sb + st * STAGEB;
        const uint32_t sBh = sAh + SLAB_A;

#pragma unroll
        for (int ks = 0; ks < 4; ks++) {
            uint32_t bh[4][4];
#pragma unroll
            for (int np = 0; np < 4; np++) {
                const uint32_t roff = SWZ128((uint32_t)(
                    (wn + np * 16 + ((lane >> 4) << 3) + (lane & 7)) * 128 +
                    ks * 32 + ((lane >> 3) & 1) * 16));
                ldm_x4(bh[np], sBh + roff);
            }
#pragma unroll
            for (int mf = 0; mf < 2; mf++) {
                const uint32_t aoff = SWZ128((uint32_t)(
                    (wm + mf * 16 + (lane & 15)) * 128 +
                    ks * 32 + ((lane >> 4) & 1) * 16));
                uint32_t ah[4];
                ldm_x4(ah, sAh + aoff);
#pragma unroll
                for (int np = 0; np < 4; np++) {
                    mma_f16(acc[mf][2 * np], ah, &bh[np][0]);
                    mma_f16(acc[mf][2 * np + 1], ah, &bh[np][2]);
                }
            }
        }

        st = (st + 1 == NSTAGE) ? 0 : st + 1;
        si = (si + 1 == NSTAGE) ? 0 : si + 1;
    }

    // epilogue
    const int r0 = lane >> 2;
    const int c0 = (lane & 3) * 2;
#pragma unroll
    for (int mf = 0; mf < 2; mf++) {
#pragma unroll
        for (int nf = 0; nf < 8; nf++) {
            const int row = row0 + wm + mf * 16 + r0;
            const int col = col0 + wn + nf * 8 + c0;
            const float x0 = acc[mf][nf][0] * alpha;
            const float x1 = acc[mf][nf][1] * alpha;
            const float x2 = acc[mf][nf][2] * alpha;
            const float x3 = acc[mf][nf][3] * alpha;
            if (omode == 0) {
                *(float2*)(C + (size_t)row * ldc + col)       = make_float2(x0, x1);
                *(float2*)(C + (size_t)(row + 8) * ldc + col) = make_float2(x2, x3);
            } else {
                *(uint32_t*)(Ch + (size_t)row * ldc + col) =
                    (uint32_t)h16(__float2half_rn(x0)) |
                    ((uint32_t)h16(__float2half_rn(x1)) << 16);
                *(uint32_t*)(Ch + (size_t)(row + 8) * ldc + col) =
                    (uint32_t)h16(__float2half_rn(x2)) |
                    ((uint32_t)h16(__float2half_rn(x3)) << 16);
            }
        }
    }
}

// ---------------------------------------------------------------------------
// PV split-K reduce: out = PSCALE_INV * sum_s part[s], fixed order.
// ---------------------------------------------------------------------------
__global__ void __launch_bounds__(256)
reduce_pv(const float* __restrict__ part, float* __restrict__ out)
{
    const size_t i4 = (size_t)blockIdx.x * blockDim.x + threadIdx.x;
    if (i4 >= (size_t)NSEQ * DIM / 4) return;
    const int row = (int)((i4 * 4) / DIM);
    const int nseg = row / 1024 + 1;
    const size_t stride4 = (size_t)NSEQ * DIM / 4;
    float4 a = ((const float4*)part)[i4];
    for (int s = 1; s < nseg; s++) {
        const float4 b = ((const float4*)part)[s * stride4 + i4];
        a.x += b.x; a.y += b.y; a.z += b.z; a.w += b.w;
    }
    a.x *= PSCALE_INV; a.y *= PSCALE_INV; a.z *= PSCALE_INV; a.w *= PSCALE_INV;
    ((float4*)out)[i4] = a;
}

// ---------------------------------------------------------------------------
// fp32 -> fp16 single convert
// ---------------------------------------------------------------------------
__global__ void conv_f32_h(const float* __restrict__ in,
                           __half* __restrict__ out, size_t n4)
{
    const size_t i = (size_t)blockIdx.x * blockDim.x + threadIdx.x;
    if (i >= n4) return;
    const float4 v = ((const float4*)in)[i];
    uint2 H;
    H.x = (uint32_t)h16(__float2half_rn(v.x)) |
          ((uint32_t)h16(__float2half_rn(v.y)) << 16);
    H.y = (uint32_t)h16(__float2half_rn(v.z)) |
          ((uint32_t)h16(__float2half_rn(v.w)) << 16);
    ((uint2*)out)[i] = H;
}

// ---------------------------------------------------------------------------
// transpose fp32 -> fp16 single
// ---------------------------------------------------------------------------
__global__ void transpose_f32_h(const float* __restrict__ in,
                                __half* __restrict__ out, int R, int C)
{
    __shared__ float t[32][33];
    const int bx = blockIdx.x * 32;
    const int by = blockIdx.y * 32;
    const int tx = threadIdx.x;
    for (int j = threadIdx.y; j < 32; j += 8)
        t[j][tx] = in[(size_t)(by + j) * C + bx + tx];
    __syncthreads();
    for (int j = threadIdx.y; j < 32; j += 8)
        out[(size_t)(bx + j) * R + by + tx] = __float2half_rn(t[tx][j]);
}

// ---------------------------------------------------------------------------
// transpose fp16 -> fp16
// ---------------------------------------------------------------------------
__global__ void transpose_h(const __half* __restrict__ in,
                            __half* __restrict__ out, int R, int C)
{
    __shared__ __half t[32][34];
    const int bx = blockIdx.x * 32;
    const int by = blockIdx.y * 32;
    const int tx = threadIdx.x;
    for (int j = threadIdx.y; j < 32; j += 8)
        t[j][tx] = in[(size_t)(by + j) * C + bx + tx];
    __syncthreads();
    for (int j = threadIdx.y; j < 32; j += 8)
        out[(size_t)(bx + j) * R + by + tx] = t[tx][j];
}

// ---------------------------------------------------------------------------
// single-pass causal row softmax: fp32 row in registers, write fp16 P scaled
// by PSCALE, zero-pad to 256-boundary.
// ---------------------------------------------------------------------------
__global__ void __launch_bounds__(256)
softmax1(const float* __restrict__ S, __half* __restrict__ P)
{
    __shared__ float red[8];
    const int row = blockIdx.x;
    const int tid = threadIdx.x;
    const int lane = tid & 31;
    const int wid = tid >> 5;
    const float* srow = S + (size_t)row * NSEQ;
    __half* prow = P + (size_t)row * NSEQ;
    const int n      = row + 1;
    const int padded = (row & ~255) + 256;

    float v[32];
    float m = -1e30f;
#pragma unroll
    for (int i = 0; i < 32; i++) {
        const int c = i * 256 + tid;
        v[i] = (c < n) ? srow[c] : -1e30f;
        m = fmaxf(m, v[i]);
    }
#pragma unroll
    for (int o = 16; o; o >>= 1) m = fmaxf(m, __shfl_xor_sync(~0u, m, o));
    if (lane == 0) red[wid] = m;
    __syncthreads();
    m = -1e30f;
#pragma unroll
    for (int w = 0; w < 8; w++) m = fmaxf(m, red[w]);
    __syncthreads();

    float sum = 0.f;
#pragma unroll
    for (int i = 0; i < 32; i++) {
        const float e = __expf(v[i] - m);
        v[i] = e;
        sum += e;
    }
#pragma unroll
    for (int o = 16; o; o >>= 1) sum += __shfl_xor_sync(~0u, sum, o);
    if (lane == 0) red[wid] = sum;
    __syncthreads();
    sum = 0.f;
#pragma unroll
    for (int w = 0; w < 8; w++) sum += red[w];
    const float inv_sc = PSCALE / sum;

#pragma unroll
    for (int i = 0; i < 32; i++) {
        const int c = i * 256 + tid;
        if (c < padded) prow[c] = __float2half_rn(v[i] * inv_sc);
    }
}

// ---------------------------------------------------------------------------
extern "C" void kernel_launch(void* const* d_in, const int* in_sizes, int n_in,
                              void* d_out, int out_size)
{
    const float* q  = (const float*)d_in[0];
    const float* k  = (const float*)d_in[1];
    const float* v  = (const float*)d_in[2];
    const float* Wq = (const float*)d_in[3];
    const float* Wk = (const float*)d_in[4];
    const float* Wv = (const float*)d_in[5];
    float* out = (float*)d_out;

    __half *qk16, *v16, *WT, *QK, *Vr, *VT, *P;
    float *S, *Opart;
    cudaGetSymbolAddress((void**)&qk16, g_qk16);
    cudaGetSymbolAddress((void**)&v16, g_v16);
    cudaGetSymbolAddress((void**)&WT, g_WT);
    cudaGetSymbolAddress((void**)&QK, g_QK);
    cudaGetSymbolAddress((void**)&Vr, g_Vr);
    cudaGetSymbolAddress((void**)&VT, g_VT);
    cudaGetSymbolAddress((void**)&S,  g_S);
    cudaGetSymbolAddress((void**)&P,  g_P);
    cudaGetSymbolAddress((void**)&Opart, g_Opart);

    const size_t WW = (size_t)DIM * DIM;
    const size_t ND = (size_t)NSEQ * DIM;
    __half* q16 = qk16;
    __half* k16 = qk16 + ND;
    __half* Qh  = QK;
    __half* Kh  = QK + ND;

    cudaFuncSetAttribute(gemm_nt, cudaFuncAttributeMaxDynamicSharedMemorySize,
                         SMEM_GEMM_BYTES);

    const dim3 blk(256);
    const dim3 tblk(32, 8);
    const size_t n4 = ND / 4;
    const unsigned gcv = (unsigned)((n4 + 255) / 256);
    const dim3 gproj(DIM / BN, NSEQ / BM, 2);        // (8, 64, 2)
    const dim3 gsc(NSEQ / BN, NSEQ / BM);            // (64, 64)
    const dim3 gpv(DIM / BN, NSEQ / BM, NSEG);       // (8, 64, 8) split-K

    // Fork-join (passes teardown): ONE side stream, two events.
    cudaStream_t side;
    cudaStreamCreateWithFlags(&side, cudaStreamNonBlocking);
    cudaEvent_t eFork, eJoin;
    cudaEventCreateWithFlags(&eFork, cudaEventDisableTiming);
    cudaEventCreateWithFlags(&eJoin, cudaEventDisableTiming);

    cudaEventRecord(eFork, 0);
    cudaStreamWaitEvent(side, eFork, 0);

    // ---- side stream: V chain ----
    conv_f32_h<<<gcv, blk, 0, side>>>(v, v16, n4);
    transpose_f32_h<<<dim3(DIM / 32, DIM / 32), tblk, 0, side>>>(
        Wv, WT + 2 * WW, DIM, DIM);
    gemm_nt<<<dim3(DIM / BN, NSEQ / BM), blk, SMEM_GEMM_BYTES, side>>>(
        v16, WT + 2 * WW, nullptr, Vr, DIM, DIM, DIM, 1.0f, DIM / BK,
        0, 2, 0, 0, 0);
    transpose_h<<<dim3(DIM / 32, NSEQ / 32), tblk, 0, side>>>(Vr, VT, NSEQ, DIM);
    cudaEventRecord(eJoin, side);

    // ---- main stream: Q/K chain ----
    conv_f32_h<<<gcv, blk>>>(q, q16, n4);
    conv_f32_h<<<gcv, blk>>>(k, k16, n4);
    transpose_f32_h<<<dim3(DIM / 32, DIM / 32), tblk>>>(Wq, WT, DIM, DIM);
    transpose_f32_h<<<dim3(DIM / 32, DIM / 32), tblk>>>(Wk, WT + WW, DIM, DIM);

    // batched Q,K projections: z selects (q16|k16, WTq|WTk, Qh|Kh)
    gemm_nt<<<gproj, blk, SMEM_GEMM_BYTES>>>(
        q16, WT, nullptr, Qh, DIM, DIM, DIM, 1.0f, DIM / BK,
        0, 2, ND, WW, ND);

    // scores: S = (Q K^T)/sqrt(Dk), causal tile skip
    gemm_nt<<<gsc, blk, SMEM_GEMM_BYTES>>>(
        Qh, Kh, S, nullptr, DIM, DIM, NSEQ, 0.03125f, DIM / BK,
        1, 0, 0, 0, 0);

    // single-pass softmax -> fp16 P (scaled by 4096)
    softmax1<<<NSEQ, blk>>>(S, P);

    // join: PV needs V^T from the side stream
    cudaStreamWaitEvent(0, eJoin, 0);

    // O = P @ (V^T)^T via split-K (16-chunk segments), partials fp32
    gemm_nt<<<gpv, blk, SMEM_GEMM_BYTES>>>(
        P, VT, Opart, nullptr, NSEQ, NSEQ, DIM, 1.0f, 16,
        3, 0, 0, 0, ND);

    // fixed-order reduce (+ 1/PSCALE)
    reduce_pv<<<gcv, blk>>>(Opart, out);
}